// round 5
// baseline (speedup 1.0000x reference)
#include <cuda_runtime.h>

// ---------------- problem constants ----------------
#define Bv 1024
#define Nv 512
#define MI 512
#define ME 16
#define NEWTON_ITERS 14
#define ADMM_IT 15
#define PGD_IT 3
#define ALPHA_C 0.05f

// ---------------- GEMM tile config ----------------
#define BM 64
#define BN 64
#define BKt 16

enum { EPI_NONE=0, EPI_ADD_I, EPI_NEWTON, EPI_SUB_FROM_D, EPI_ADD_D,
       EPI_ADD_ROW, EPI_ADD_D_ROW, EPI_INIT_WU };

// ---------------- scratch layout ----------------
constexpr size_t SZ_MAT  = 512*512;
constexpr size_t SZ_BAT  = (size_t)Bv*512;
constexpr size_t OFF_M  = 0;
constexpr size_t OFF_XA = OFF_M  + SZ_MAT;
constexpr size_t OFF_XB = OFF_XA + SZ_MAT;
constexpr size_t OFF_T  = OFF_XB + SZ_MAT;
constexpr size_t OFF_P  = OFF_T  + SZ_MAT;
constexpr size_t OFF_GP = OFF_P  + SZ_MAT;
constexpr size_t OFF_V  = OFF_GP + SZ_MAT;
constexpr size_t OFF_AMI= OFF_V  + SZ_MAT;        // 16*512
constexpr size_t OFF_S  = OFF_AMI + (size_t)ME*Nv;
constexpr size_t OFF_SI = OFF_S  + (size_t)ME*ME;
constexpr size_t OFF_W  = OFF_SI + (size_t)ME*ME;
constexpr size_t OFF_Q0 = OFF_W  + (size_t)Nv*ME;
constexpr size_t OFF_G0 = OFF_Q0 + Nv;
constexpr size_t OFF_CV = OFF_G0 + MI;
constexpr size_t OFF_X  = OFF_CV + 64;
constexpr size_t OFF_Y  = OFF_X  + SZ_BAT;
constexpr size_t OFF_D  = OFF_Y  + SZ_BAT;
constexpr size_t OFF_XP = OFF_D  + SZ_BAT;
constexpr size_t OFF_WB = OFF_XP + SZ_BAT;
constexpr size_t OFF_UB = OFF_WB + SZ_BAT;
constexpr size_t OFF_GZ = OFF_UB + SZ_BAT;
constexpr size_t SCRATCH_FLOATS = OFF_GZ + SZ_BAT;

__device__ float g_scratch[SCRATCH_FLOATS];

// ---------------- generic tiled GEMM ----------------
// C (M x N) = opA(A) @ opB(B) with epilogue.
// TA=1: A stored (K x M) row-major (i.e. logical A = stored^T)
// TB=1: B stored (N x K) row-major (i.e. logical B = stored^T)
template<int TA, int TB>
__global__ void gemm_k(int M, int N, int K,
    const float* __restrict__ A, int lda,
    const float* __restrict__ B, int ldb,
    float* __restrict__ C, int ldc,
    const float* __restrict__ D,
    const float* __restrict__ row,
    float* __restrict__ C2,
    int epi)
{
    __shared__ float As[BKt][BM];
    __shared__ float Bs[BKt][BN];
    const int i0 = blockIdx.y * BM;
    const int j0 = blockIdx.x * BN;
    const int tid = threadIdx.x;
    const int tx = tid & 15, ty = tid >> 4;

    float acc[4][4];
#pragma unroll
    for (int m = 0; m < 4; m++)
#pragma unroll
        for (int n = 0; n < 4; n++) acc[m][n] = 0.f;

    for (int k0 = 0; k0 < K; k0 += BKt) {
#pragma unroll
        for (int l = 0; l < 4; l++) {
            int idx = tid + l * 256;
            if (TA == 0) {
                int mm = idx >> 4, kk = idx & 15;
                int gi = i0 + mm, gk = k0 + kk;
                As[kk][mm] = (gi < M && gk < K) ? A[(size_t)gi * lda + gk] : 0.f;
            } else {
                int mm = idx & 63, kk = idx >> 6;
                int gi = i0 + mm, gk = k0 + kk;
                As[kk][mm] = (gi < M && gk < K) ? A[(size_t)gk * lda + gi] : 0.f;
            }
            if (TB == 0) {
                int nn = idx & 63, kk = idx >> 6;
                int gj = j0 + nn, gk = k0 + kk;
                Bs[kk][nn] = (gj < N && gk < K) ? B[(size_t)gk * ldb + gj] : 0.f;
            } else {
                int kk = idx & 15, nn = idx >> 4;
                int gj = j0 + nn, gk = k0 + kk;
                Bs[kk][nn] = (gj < N && gk < K) ? B[(size_t)gj * ldb + gk] : 0.f;
            }
        }
        __syncthreads();
#pragma unroll
        for (int kk = 0; kk < BKt; kk++) {
            float a[4], bb[4];
#pragma unroll
            for (int m = 0; m < 4; m++) a[m] = As[kk][ty * 4 + m];
#pragma unroll
            for (int n = 0; n < 4; n++) bb[n] = Bs[kk][tx * 4 + n];
#pragma unroll
            for (int m = 0; m < 4; m++)
#pragma unroll
                for (int n = 0; n < 4; n++)
                    acc[m][n] = fmaf(a[m], bb[n], acc[m][n]);
        }
        __syncthreads();
    }

#pragma unroll
    for (int m = 0; m < 4; m++) {
        int gi = i0 + ty * 4 + m;
        if (gi >= M) continue;
#pragma unroll
        for (int n = 0; n < 4; n++) {
            int gj = j0 + tx * 4 + n;
            if (gj >= N) continue;
            float v = acc[m][n];
            size_t o = (size_t)gi * ldc + gj;
            switch (epi) {
                case EPI_ADD_I:      C[o] = v + ((gi == gj) ? 1.f : 0.f); break;
                case EPI_NEWTON:     C[o] = 2.f * D[o] - v;               break;
                case EPI_SUB_FROM_D: C[o] = D[o] - v;                     break;
                case EPI_ADD_D:      C[o] = D[o] + v;                     break;
                case EPI_ADD_ROW:    C[o] = v + row[gj];                  break;
                case EPI_ADD_D_ROW:  C[o] = D[o] + v + row[gj];           break;
                case EPI_INIT_WU:    C[o] = fminf(row[gj], v); C2[o] = 0.f; break;
                default:             C[o] = v;                            break;
            }
        }
    }
}

// ---------------- small helper kernels ----------------

// r = max row abs-sum of Mmat (512x512); cval = 2/(1+r)
__global__ void rowmax_kernel(const float* __restrict__ Mm, float* __restrict__ cval) {
    __shared__ float red[512];
    int i = threadIdx.x;
    float s = 0.f;
    for (int j = 0; j < 512; j++) s += fabsf(Mm[(size_t)i * 512 + j]);
    red[i] = s;
    __syncthreads();
    for (int st = 256; st > 0; st >>= 1) {
        if (i < st) red[i] = fmaxf(red[i], red[i + st]);
        __syncthreads();
    }
    if (i == 0) *cval = 2.0f / (1.0f + red[0]);
}

// X = cval * I (512x512)
__global__ void initX_kernel(float* __restrict__ X, const float* __restrict__ cval) {
    int idx = blockIdx.x * blockDim.x + threadIdx.x;
    if (idx < 512 * 512) {
        int i = idx >> 9, j = idx & 511;
        X[idx] = (i == j) ? *cval : 0.f;
    }
}

// Gauss-Jordan inverse of SPD 16x16 (no pivoting), one block of 256 threads.
__global__ void sinv_kernel(const float* __restrict__ S, float* __restrict__ Si) {
    __shared__ float a[16][32];
    int t = threadIdx.x;
    for (int l = 0; l < 2; l++) {
        int idx = t + l * 256;
        int r = idx >> 5, c = idx & 31;
        a[r][c] = (c < 16) ? S[r * 16 + c] : ((c - 16 == r) ? 1.f : 0.f);
    }
    __syncthreads();
    for (int p = 0; p < 16; p++) {
        float pivinv = 1.0f / a[p][p];
        float oldv[2], oldpc[2], oldrp[2];
        int rr[2], cc[2];
        for (int l = 0; l < 2; l++) {
            int idx = t + l * 256;
            int r = idx >> 5, c = idx & 31;
            rr[l] = r; cc[l] = c;
            oldv[l]  = a[r][c];
            oldpc[l] = a[p][c];
            oldrp[l] = a[r][p];
        }
        __syncthreads();
        for (int l = 0; l < 2; l++) {
            int r = rr[l], c = cc[l];
            a[r][c] = (r == p) ? oldv[l] * pivinv
                               : oldv[l] - oldrp[l] * pivinv * oldpc[l];
        }
        __syncthreads();
    }
    for (int l = 0; l < 2; l++) {
        int idx = t + l * 256;
        int r = idx >> 5, c = idx & 31;
        if (c >= 16) Si[r * 16 + (c - 16)] = a[r][c];
    }
}

// q0 = W @ b  (512x16 * 16)
__global__ void q0_kernel(const float* __restrict__ W, const float* __restrict__ b,
                          float* __restrict__ q0) {
    int i = threadIdx.x;
    if (i < 512) {
        float s = 0.f;
        for (int j = 0; j < 16; j++) s += W[i * 16 + j] * b[j];
        q0[i] = s;
    }
}

// g0 = G @ q0  (512x512 * 512)
__global__ void g0_kernel(const float* __restrict__ G, const float* __restrict__ q0,
                          float* __restrict__ g0) {
    int i = blockIdx.x * blockDim.x + threadIdx.x;
    if (i < MI) {
        float s = 0.f;
        for (int j = 0; j < Nv; j++) s += G[(size_t)i * Nv + j] * q0[j];
        g0[i] = s;
    }
}

// ADMM state update: t = h - Gz - u ; u = relu(-t) ; w = h - |t|
__global__ void update_kernel(const float* __restrict__ Gz, float* __restrict__ u,
                              float* __restrict__ w, const float* __restrict__ h) {
    int idx = blockIdx.x * blockDim.x + threadIdx.x;
    if (idx < Bv * MI) {
        int j = idx & (MI - 1);
        float t = h[j] - Gz[idx] - u[idx];
        u[idx] = fmaxf(-t, 0.f);
        w[idx] = h[j] - fabsf(t);
    }
}

// PGD step: y = (1-alpha)*x + alpha*c
__global__ void pgd_kernel(const float* __restrict__ x, const float* __restrict__ c,
                           float* __restrict__ y) {
    int idx = blockIdx.x * blockDim.x + threadIdx.x;
    if (idx < Bv * Nv) y[idx] = x[idx] - ALPHA_C * (x[idx] - c[idx]);
}

// ---------------- host-side launch helpers ----------------
static void gemm(int ta, int tb, int M, int N, int K,
                 const float* A, int lda, const float* B, int ldb,
                 float* C, int ldc,
                 const float* D, const float* row, float* C2, int epi)
{
    dim3 grid((N + BN - 1) / BN, (M + BM - 1) / BM);
    dim3 blk(256);
    if (!ta && !tb)      gemm_k<0,0><<<grid, blk>>>(M,N,K,A,lda,B,ldb,C,ldc,D,row,C2,epi);
    else if (!ta && tb)  gemm_k<0,1><<<grid, blk>>>(M,N,K,A,lda,B,ldb,C,ldc,D,row,C2,epi);
    else                 gemm_k<1,0><<<grid, blk>>>(M,N,K,A,lda,B,ldb,C,ldc,D,row,C2,epi);
}

extern "C" void kernel_launch(void* const* d_in, const int* in_sizes, int n_in,
                              void* d_out, int out_size)
{
    (void)in_sizes; (void)n_in; (void)out_size;
    const float* c = (const float*)d_in[0];   // [B, N]
    const float* G = (const float*)d_in[1];   // [MI, N]
    const float* h = (const float*)d_in[2];   // [MI]
    const float* Am= (const float*)d_in[3];   // [ME, N]
    const float* b = (const float*)d_in[4];   // [ME]
    float* out = (float*)d_out;               // [B, N]

    float* S;
    cudaGetSymbolAddress((void**)&S, g_scratch);
    float* Mm  = S + OFF_M;
    float* Xa  = S + OFF_XA;
    float* Xb  = S + OFF_XB;
    float* Tt  = S + OFF_T;
    float* P   = S + OFF_P;
    float* GP  = S + OFF_GP;
    float* V   = S + OFF_V;
    float* AMi = S + OFF_AMI;
    float* Ss  = S + OFF_S;
    float* Si  = S + OFF_SI;
    float* W   = S + OFF_W;
    float* q0  = S + OFF_Q0;
    float* g0  = S + OFF_G0;
    float* cv  = S + OFF_CV;
    float* xb  = S + OFF_X;
    float* yb  = S + OFF_Y;
    float* db  = S + OFF_D;
    float* xPb = S + OFF_XP;
    float* wb  = S + OFF_WB;
    float* ub  = S + OFF_UB;
    float* Gzb = S + OFF_GZ;

    // ===== Precompute (per launch, deterministic) =====
    // 1) M = G^T G + I   (512x512)
    gemm(1, 0, Nv, Nv, MI, G, Nv, G, Nv, Mm, Nv, nullptr, nullptr, nullptr, EPI_ADD_I);
    // 2) cval = 2/(1+||M||_inf); X0 = cval*I
    rowmax_kernel<<<1, 512>>>(Mm, cv);
    initX_kernel<<<(512 * 512 + 255) / 256, 256>>>(Xa, cv);
    // 3) Newton-Schulz: X <- 2X - X M X
    float* cur = Xa; float* nxt = Xb;
    for (int it = 0; it < NEWTON_ITERS; it++) {
        gemm(0, 0, Nv, Nv, Nv, Mm, Nv, cur, Nv, Tt, Nv, nullptr, nullptr, nullptr, EPI_NONE);
        gemm(0, 0, Nv, Nv, Nv, cur, Nv, Tt, Nv, nxt, Nv, cur, nullptr, nullptr, EPI_NEWTON);
        float* tmp = cur; cur = nxt; nxt = tmp;
    }
    float* Minv = cur;
    // 4) AMi = A @ Minv    (16 x 512)
    gemm(0, 0, ME, Nv, Nv, Am, Nv, Minv, Nv, AMi, Nv, nullptr, nullptr, nullptr, EPI_NONE);
    // 5) S = AMi @ A^T     (16 x 16)
    gemm(0, 1, ME, ME, Nv, AMi, Nv, Am, Nv, Ss, ME, nullptr, nullptr, nullptr, EPI_NONE);
    // 6) Si = inv(S)
    sinv_kernel<<<1, 256>>>(Ss, Si);
    // 7) W = AMi^T @ Si    (512 x 16)   [AMi^T = Minv A^T]
    gemm(1, 0, Nv, ME, ME, AMi, Nv, Si, ME, W, ME, nullptr, nullptr, nullptr, EPI_NONE);
    // 8) P = Minv - W @ AMi  (512x512, k=16 rank correction)
    gemm(0, 0, Nv, Nv, ME, W, ME, AMi, Nv, P, Nv, Minv, nullptr, nullptr, EPI_SUB_FROM_D);
    // 9) GP = G @ P         (512x512)
    gemm(0, 0, MI, Nv, Nv, G, Nv, P, Nv, GP, Nv, nullptr, nullptr, nullptr, EPI_NONE);
    // 10) V = GP @ G^T      (512x512)
    gemm(0, 1, MI, MI, Nv, GP, Nv, G, Nv, V, MI, nullptr, nullptr, nullptr, EPI_NONE);
    // 11) q0 = W @ b ; g0 = G @ q0
    q0_kernel<<<1, 512>>>(W, b, q0);
    g0_kernel<<<2, 256>>>(G, q0, g0);

    // ===== Projection: zout = Proj(xin) =====
    auto project = [&](const float* xin, float* zout) {
        // init: acc = xin @ G^T ; w = min(h, acc) ; u = 0
        gemm(0, 1, Bv, MI, Nv, xin, Nv, G, Nv, wb, MI, nullptr, h, ub, EPI_INIT_WU);
        // d = xin @ GP^T + g0   (= x @ (P G^T) + g0)
        gemm(0, 1, Bv, MI, Nv, xin, Nv, GP, Nv, db, MI, nullptr, g0, nullptr, EPI_ADD_ROW);
        // xP = xin @ P
        gemm(0, 0, Bv, Nv, Nv, xin, Nv, P, Nv, xPb, Nv, nullptr, nullptr, nullptr, EPI_NONE);
        // ADMM iterations
        for (int it = 0; it < ADMM_IT; it++) {
            gemm(0, 0, Bv, MI, MI, wb, MI, V, MI, Gzb, MI, db, nullptr, nullptr, EPI_ADD_D);
            update_kernel<<<(Bv * MI + 255) / 256, 256>>>(Gzb, ub, wb, h);
        }
        // final z = xP + w @ GP + q0
        gemm(0, 0, Bv, Nv, MI, wb, MI, GP, Nv, zout, Nv, xPb, q0, nullptr, EPI_ADD_D_ROW);
    };

    // ===== PGD =====
    project(c, xb);
    for (int i = 0; i < PGD_IT; i++) {
        pgd_kernel<<<(Bv * Nv + 255) / 256, 256>>>(xb, c, yb);
        project(yb, (i == PGD_IT - 1) ? out : xb);
    }
}

// round 8
// speedup vs baseline: 1.5699x; 1.5699x over previous
#include <cuda_runtime.h>

// ---------------- problem constants ----------------
#define Bv 1024
#define Nv 512
#define MI 512
#define ME 16
#define NEWTON_ITERS 9
#define ADMM_IT 15
#define ALPHA_C 0.05f

enum { EPI_NONE=0, EPI_ADD_I, EPI_NEWTON, EPI_SUB_FROM_D,
       EPI_ADD_ROW, EPI_ADD_D_ROW, EPI_INIT_WU, EPI_ADMM, EPI_FINAL_PGD };

// ---------------- scratch layout ----------------
constexpr size_t SZ_MAT  = 512*512;
constexpr size_t SZ_BAT  = (size_t)Bv*512;
constexpr size_t OFF_M   = 0;
constexpr size_t OFF_XA  = OFF_M  + SZ_MAT;
constexpr size_t OFF_XB  = OFF_XA + SZ_MAT;
constexpr size_t OFF_T   = OFF_XB + SZ_MAT;
constexpr size_t OFF_P   = OFF_T  + SZ_MAT;
constexpr size_t OFF_GP  = OFF_P  + SZ_MAT;
constexpr size_t OFF_V   = OFF_GP + SZ_MAT;
constexpr size_t OFF_AMI = OFF_V  + SZ_MAT;          // 16*512
constexpr size_t OFF_S   = OFF_AMI + (size_t)ME*Nv;  // 16*16
constexpr size_t OFF_SI  = OFF_S  + (size_t)ME*ME;
constexpr size_t OFF_W   = OFF_SI + (size_t)ME*ME;   // 512*16
constexpr size_t OFF_Q0  = OFF_W  + (size_t)Nv*ME;
constexpr size_t OFF_G0  = OFF_Q0 + Nv;
constexpr size_t OFF_CV  = OFF_G0 + MI;
constexpr size_t OFF_X   = OFF_CV + 64;
constexpr size_t OFF_Y   = OFF_X  + SZ_BAT;
constexpr size_t OFF_D   = OFF_Y  + SZ_BAT;
constexpr size_t OFF_XP  = OFF_D  + SZ_BAT;
constexpr size_t OFF_WB  = OFF_XP + SZ_BAT;
constexpr size_t OFF_W2  = OFF_WB + SZ_BAT;
constexpr size_t OFF_UB  = OFF_W2 + SZ_BAT;
constexpr size_t SCRATCH_FLOATS = OFF_UB + SZ_BAT;

// 256B alignment: every float4 / 128-bit access derived from 16-float-multiple
// offsets is then guaranteed 16B-aligned (misaligned LDG.128 traps err715).
__device__ __align__(256) float g_scratch[SCRATCH_FLOATS];

// ---------------- packed f32x2 helpers (FFMA2 path, PTX-only) ----------------
__device__ __forceinline__ unsigned long long pack2(float x, float y) {
    unsigned long long r;
    asm("mov.b64 %0, {%1, %2};" : "=l"(r) : "f"(x), "f"(y));
    return r;
}
__device__ __forceinline__ void unpack2(unsigned long long v, float &x, float &y) {
    asm("mov.b64 {%0, %1}, %2;" : "=f"(x), "=f"(y) : "l"(v));
}
__device__ __forceinline__ void fma2(unsigned long long &d, unsigned long long a,
                                     unsigned long long b) {
    asm("fma.rn.f32x2 %0, %1, %2, %0;" : "+l"(d) : "l"(a), "l"(b));
}

// ---------------- FFMA2 tiled GEMM ----------------
// C (M x N) = opA(A) @ opB(B) with fused epilogue.
// TA=1: A stored (K x M); TB=1: B stored (N x K). 256 threads.
// Thread grid 16x16; thread tile (BMt/16) x (BNt/16). Double-buffered BK=16.
template<int TA, int TB, int BMt, int BNt>
__global__ __launch_bounds__(256)
void gemm_k(int M, int N, int K,
            const float* __restrict__ A, int lda,
            const float* __restrict__ B, int ldb,
            float* __restrict__ C, int ldc,
            const float* __restrict__ D,
            const float* __restrict__ row,
            float* __restrict__ C2,
            const float* __restrict__ C3,
            int epi)
{
    constexpr int TM = BMt / 16, TN = BNt / 16;
    constexpr int NP = TN / 2;
    __shared__ __align__(16) float As[2][16][BMt];
    __shared__ __align__(16) float Bs[2][16][BNt];

    const int tid = threadIdx.x;
    const int tx = tid & 15, ty = tid >> 4;
    const int i0 = blockIdx.y * BMt;
    const int j0 = blockIdx.x * BNt;

    constexpr int AF4 = BMt * 4;  // float4 slots per A tile (BMt*16/4)
    constexpr int BF4 = BNt * 4;
    const bool a_act = tid < AF4;
    const bool b_act = tid < BF4;
    int a_r0, a_r1, b_r0, b_r1;
    if (TA == 0) { a_r0 = tid >> 2;          a_r1 = tid & 3; }            // row, kq
    else         { a_r0 = tid / (BMt / 4);   a_r1 = tid % (BMt / 4); }    // krow, mq
    if (TB == 0) { b_r0 = tid / (BNt / 4);   b_r1 = tid % (BNt / 4); }    // krow, nq
    else         { b_r0 = tid >> 2;          b_r1 = tid & 3; }            // nrow, kq

    float4 pa = make_float4(0.f, 0.f, 0.f, 0.f);
    float4 pb = make_float4(0.f, 0.f, 0.f, 0.f);

    auto loadA = [&](int k0) {
        if (!a_act) return;
        if (TA == 0) {
            int gi = i0 + a_r0;
            pa = (gi < M) ? *reinterpret_cast<const float4*>(&A[(size_t)gi * lda + k0 + a_r1 * 4])
                          : make_float4(0.f, 0.f, 0.f, 0.f);
        } else {
            int gm = i0 + a_r1 * 4;
            pa = (gm < M) ? *reinterpret_cast<const float4*>(&A[(size_t)(k0 + a_r0) * lda + gm])
                          : make_float4(0.f, 0.f, 0.f, 0.f);
        }
    };
    auto storeA = [&](int buf) {
        if (!a_act) return;
        if (TA == 0) {
            As[buf][a_r1 * 4 + 0][a_r0] = pa.x;
            As[buf][a_r1 * 4 + 1][a_r0] = pa.y;
            As[buf][a_r1 * 4 + 2][a_r0] = pa.z;
            As[buf][a_r1 * 4 + 3][a_r0] = pa.w;
        } else {
            *reinterpret_cast<float4*>(&As[buf][a_r0][a_r1 * 4]) = pa;
        }
    };
    auto loadB = [&](int k0) {
        if (!b_act) return;
        if (TB == 0) {
            int gj = j0 + b_r1 * 4;
            pb = (gj < N) ? *reinterpret_cast<const float4*>(&B[(size_t)(k0 + b_r0) * ldb + gj])
                          : make_float4(0.f, 0.f, 0.f, 0.f);
        } else {
            int gn = j0 + b_r0;
            pb = (gn < N) ? *reinterpret_cast<const float4*>(&B[(size_t)gn * ldb + k0 + b_r1 * 4])
                          : make_float4(0.f, 0.f, 0.f, 0.f);
        }
    };
    auto storeB = [&](int buf) {
        if (!b_act) return;
        if (TB == 0) {
            *reinterpret_cast<float4*>(&Bs[buf][b_r0][b_r1 * 4]) = pb;
        } else {
            Bs[buf][b_r1 * 4 + 0][b_r0] = pb.x;
            Bs[buf][b_r1 * 4 + 1][b_r0] = pb.y;
            Bs[buf][b_r1 * 4 + 2][b_r0] = pb.z;
            Bs[buf][b_r1 * 4 + 3][b_r0] = pb.w;
        }
    };

    unsigned long long acc[TM][NP];
#pragma unroll
    for (int m = 0; m < TM; m++)
#pragma unroll
        for (int p = 0; p < NP; p++) acc[m][p] = 0ULL;

    loadA(0); loadB(0);
    storeA(0); storeB(0);
    __syncthreads();

    const int nk = K >> 4;
    int buf = 0;
    for (int t = 0; t < nk; t++) {
        if (t + 1 < nk) { loadA((t + 1) * 16); loadB((t + 1) * 16); }
#pragma unroll
        for (int kk = 0; kk < 16; kk++) {
            float a[TM];
            if (TM == 4) {
                float4 av = *reinterpret_cast<const float4*>(&As[buf][kk][ty * TM]);
                a[0] = av.x; a[1] = av.y; a[2] = av.z; a[3] = av.w;
            } else {
                float2 av = *reinterpret_cast<const float2*>(&As[buf][kk][ty * TM]);
                a[0] = av.x; a[1] = av.y;
            }
            unsigned long long bv[NP];
            if (NP == 2) {
                ulonglong2 t2 = *reinterpret_cast<const ulonglong2*>(&Bs[buf][kk][tx * TN]);
                bv[0] = t2.x; bv[1] = t2.y;
            } else {
                bv[0] = *reinterpret_cast<const unsigned long long*>(&Bs[buf][kk][tx * TN]);
            }
#pragma unroll
            for (int m = 0; m < TM; m++) {
                unsigned long long am = pack2(a[m], a[m]);
#pragma unroll
                for (int p = 0; p < NP; p++) fma2(acc[m][p], am, bv[p]);
            }
        }
        if (t + 1 < nk) { storeA(buf ^ 1); storeB(buf ^ 1); __syncthreads(); buf ^= 1; }
    }

    // ---- fused epilogue ----
#pragma unroll
    for (int m = 0; m < TM; m++) {
        int gi = i0 + ty * TM + m;
        if (gi >= M) continue;
#pragma unroll
        for (int p = 0; p < NP; p++) {
            float v0, v1;
            unpack2(acc[m][p], v0, v1);
#pragma unroll
            for (int e = 0; e < 2; e++) {
                int jj = j0 + tx * TN + p * 2 + e;
                if (jj >= N) continue;
                float v = e ? v1 : v0;
                size_t o = (size_t)gi * ldc + jj;
                switch (epi) {
                    case EPI_ADD_I:      C[o] = v + ((gi == jj) ? 1.f : 0.f); break;
                    case EPI_NEWTON:     C[o] = 2.f * D[o] - v;               break;
                    case EPI_SUB_FROM_D: C[o] = D[o] - v;                     break;
                    case EPI_ADD_ROW:    C[o] = v + row[jj];                  break;
                    case EPI_ADD_D_ROW:  C[o] = D[o] + v + row[jj];           break;
                    case EPI_INIT_WU:    C[o] = fminf(row[jj], v); C2[o] = 0.f; break;
                    case EPI_ADMM: {
                        float tt = row[jj] - (v + D[o]) - C2[o];
                        C2[o] = fmaxf(-tt, 0.f);
                        C[o]  = row[jj] - fabsf(tt);
                    } break;
                    case EPI_FINAL_PGD: {
                        float z = D[o] + v + row[jj];
                        C[o] = z - ALPHA_C * (z - C3[o]);
                    } break;
                    default:             C[o] = v;                            break;
                }
            }
        }
    }
}

// ---------------- small helper kernels ----------------
__global__ void rowmax_kernel(const float* __restrict__ Mm, float* __restrict__ cval) {
    __shared__ float red[512];
    int i = threadIdx.x;
    float s = 0.f;
    for (int j = 0; j < 512; j++) s += fabsf(Mm[(size_t)i * 512 + j]);
    red[i] = s;
    __syncthreads();
    for (int st = 256; st > 0; st >>= 1) {
        if (i < st) red[i] = fmaxf(red[i], red[i + st]);
        __syncthreads();
    }
    if (i == 0) *cval = 2.0f / (1.0f + red[0]);
}

__global__ void initX_kernel(float* __restrict__ X, const float* __restrict__ cval) {
    int idx = blockIdx.x * blockDim.x + threadIdx.x;
    if (idx < 512 * 512) {
        int i = idx >> 9, j = idx & 511;
        X[idx] = (i == j) ? *cval : 0.f;
    }
}

__global__ void sinv_kernel(const float* __restrict__ S, float* __restrict__ Si) {
    __shared__ float a[16][32];
    int t = threadIdx.x;
    for (int l = 0; l < 2; l++) {
        int idx = t + l * 256;
        int r = idx >> 5, c = idx & 31;
        a[r][c] = (c < 16) ? S[r * 16 + c] : ((c - 16 == r) ? 1.f : 0.f);
    }
    __syncthreads();
    for (int p = 0; p < 16; p++) {
        float pivinv = 1.0f / a[p][p];
        float oldv[2], oldpc[2], oldrp[2];
        int rr[2], cc[2];
        for (int l = 0; l < 2; l++) {
            int idx = t + l * 256;
            int r = idx >> 5, c = idx & 31;
            rr[l] = r; cc[l] = c;
            oldv[l]  = a[r][c];
            oldpc[l] = a[p][c];
            oldrp[l] = a[r][p];
        }
        __syncthreads();
        for (int l = 0; l < 2; l++) {
            int r = rr[l], c = cc[l];
            a[r][c] = (r == p) ? oldv[l] * pivinv
                               : oldv[l] - oldrp[l] * pivinv * oldpc[l];
        }
        __syncthreads();
    }
    for (int l = 0; l < 2; l++) {
        int idx = t + l * 256;
        int r = idx >> 5, c = idx & 31;
        if (c >= 16) Si[r * 16 + (c - 16)] = a[r][c];
    }
}

__global__ void q0_kernel(const float* __restrict__ W, const float* __restrict__ b,
                          float* __restrict__ q0) {
    int i = threadIdx.x;
    if (i < 512) {
        float s = 0.f;
        for (int j = 0; j < 16; j++) s += W[i * 16 + j] * b[j];
        q0[i] = s;
    }
}

__global__ void g0_kernel(const float* __restrict__ G, const float* __restrict__ q0,
                          float* __restrict__ g0) {
    int i = blockIdx.x * blockDim.x + threadIdx.x;
    if (i < MI) {
        float s = 0.f;
        for (int j = 0; j < Nv; j++) s += G[(size_t)i * Nv + j] * q0[j];
        g0[i] = s;
    }
}

// ---------------- host-side dispatch ----------------
// sq=1: 32x64 tiles (square/precompute GEMMs -> >=128 blocks). sq=0: 64x64 (batched).
static void gemm(int ta, int tb, int sq, int M, int N, int K,
                 const float* A, int lda, const float* B, int ldb,
                 float* C, int ldc,
                 const float* D, const float* row, float* C2, const float* C3, int epi)
{
    dim3 blk(256);
    if (sq) {
        dim3 grid((N + 63) / 64, (M + 31) / 32);
        if (ta)      gemm_k<1,0,32,64><<<grid, blk>>>(M,N,K,A,lda,B,ldb,C,ldc,D,row,C2,C3,epi);
        else if (tb) gemm_k<0,1,32,64><<<grid, blk>>>(M,N,K,A,lda,B,ldb,C,ldc,D,row,C2,C3,epi);
        else         gemm_k<0,0,32,64><<<grid, blk>>>(M,N,K,A,lda,B,ldb,C,ldc,D,row,C2,C3,epi);
    } else {
        dim3 grid((N + 63) / 64, (M + 63) / 64);
        if (ta)      gemm_k<1,0,64,64><<<grid, blk>>>(M,N,K,A,lda,B,ldb,C,ldc,D,row,C2,C3,epi);
        else if (tb) gemm_k<0,1,64,64><<<grid, blk>>>(M,N,K,A,lda,B,ldb,C,ldc,D,row,C2,C3,epi);
        else         gemm_k<0,0,64,64><<<grid, blk>>>(M,N,K,A,lda,B,ldb,C,ldc,D,row,C2,C3,epi);
    }
}

extern "C" void kernel_launch(void* const* d_in, const int* in_sizes, int n_in,
                              void* d_out, int out_size)
{
    (void)in_sizes; (void)n_in; (void)out_size;
    const float* c = (const float*)d_in[0];   // [B, N]
    const float* G = (const float*)d_in[1];   // [MI, N]
    const float* h = (const float*)d_in[2];   // [MI]
    const float* Am= (const float*)d_in[3];   // [ME, N]
    const float* b = (const float*)d_in[4];   // [ME]
    float* out = (float*)d_out;               // [B, N]

    float* S;
    cudaGetSymbolAddress((void**)&S, g_scratch);
    float* Mm  = S + OFF_M;
    float* Xa  = S + OFF_XA;
    float* Xb  = S + OFF_XB;
    float* Tt  = S + OFF_T;
    float* P   = S + OFF_P;
    float* GP  = S + OFF_GP;
    float* V   = S + OFF_V;
    float* AMi = S + OFF_AMI;
    float* Ss  = S + OFF_S;
    float* Si  = S + OFF_SI;
    float* W   = S + OFF_W;
    float* q0  = S + OFF_Q0;
    float* g0  = S + OFF_G0;
    float* cv  = S + OFF_CV;
    float* xb  = S + OFF_X;
    float* yb  = S + OFF_Y;
    float* db  = S + OFF_D;
    float* xPb = S + OFF_XP;
    float* wb  = S + OFF_WB;
    float* w2  = S + OFF_W2;
    float* ub  = S + OFF_UB;

    // ===== Precompute =====
    // 1) M = G^T G + I
    gemm(1,0,1, Nv, Nv, MI, G, Nv, G, Nv, Mm, Nv, nullptr, nullptr, nullptr, nullptr, EPI_ADD_I);
    // 2) X0 = (2/(1+||M||_inf)) * I  (lambda_min(M)=1 => e0=(r-1)/(r+1), 9 Newton iters suffice)
    rowmax_kernel<<<1, 512>>>(Mm, cv);
    initX_kernel<<<(512 * 512 + 255) / 256, 256>>>(Xa, cv);
    // 3) Newton-Schulz: X <- 2X - X M X
    float* cur = Xa; float* nxt = Xb;
    for (int it = 0; it < NEWTON_ITERS; it++) {
        gemm(0,0,1, Nv, Nv, Nv, Mm, Nv, cur, Nv, Tt, Nv, nullptr, nullptr, nullptr, nullptr, EPI_NONE);
        gemm(0,0,1, Nv, Nv, Nv, cur, Nv, Tt, Nv, nxt, Nv, cur, nullptr, nullptr, nullptr, EPI_NEWTON);
        float* tmp = cur; cur = nxt; nxt = tmp;
    }
    float* Minv = cur;
    // 4-8) Schur pieces
    gemm(0,0,1, ME, Nv, Nv, Am, Nv, Minv, Nv, AMi, Nv, nullptr, nullptr, nullptr, nullptr, EPI_NONE);
    gemm(0,1,1, ME, ME, Nv, AMi, Nv, Am, Nv, Ss, ME, nullptr, nullptr, nullptr, nullptr, EPI_NONE);
    sinv_kernel<<<1, 256>>>(Ss, Si);
    gemm(1,0,1, Nv, ME, ME, AMi, Nv, Si, ME, W, ME, nullptr, nullptr, nullptr, nullptr, EPI_NONE);
    gemm(0,0,1, Nv, Nv, ME, W, ME, AMi, Nv, P, Nv, Minv, nullptr, nullptr, nullptr, EPI_SUB_FROM_D);
    // 9-10) GP = G@P ; V = GP@G^T
    gemm(0,0,1, MI, Nv, Nv, G, Nv, P, Nv, GP, Nv, nullptr, nullptr, nullptr, nullptr, EPI_NONE);
    gemm(0,1,1, MI, MI, Nv, GP, Nv, G, Nv, V, MI, nullptr, nullptr, nullptr, nullptr, EPI_NONE);
    // 11) q0 = W@b ; g0 = G@q0
    q0_kernel<<<1, 512>>>(W, b, q0);
    g0_kernel<<<2, 256>>>(G, q0, g0);

    // ===== Projection with fused ADMM epilogue =====
    // last_epi: EPI_FINAL_PGD fuses z - alpha*(z - c); EPI_ADD_D_ROW is plain z.
    auto project = [&](const float* xin, float* zout, int last_epi) {
        // w = min(h, x G^T), u = 0
        gemm(0,1,0, Bv, MI, Nv, xin, Nv, G,  Nv, wb,  MI, nullptr, h,  ub,      nullptr, EPI_INIT_WU);
        // d = x GP^T + g0
        gemm(0,1,0, Bv, MI, Nv, xin, Nv, GP, Nv, db,  MI, nullptr, g0, nullptr, nullptr, EPI_ADD_ROW);
        // xP = x P
        gemm(0,0,0, Bv, Nv, Nv, xin, Nv, P,  Nv, xPb, Nv, nullptr, nullptr, nullptr, nullptr, EPI_NONE);
        // ADMM: Gz = w@V + d; t = h-Gz-u; u' = relu(-t); w' = h-|t|  (w ping-pong, u in-place)
        float* wcur = wb; float* wnext = w2;
        for (int it = 0; it < ADMM_IT; it++) {
            gemm(0,0,0, Bv, MI, MI, wcur, MI, V, MI, wnext, MI, db, h, ub, nullptr, EPI_ADMM);
            float* tmp = wcur; wcur = wnext; wnext = tmp;
        }
        // z = xP + w@GP + q0  (+ fused PGD toward c when last_epi==EPI_FINAL_PGD)
        gemm(0,0,0, Bv, Nv, MI, wcur, MI, GP, Nv, zout, Nv, xPb, q0, nullptr, c, last_epi);
    };

    // ===== PGD (pgd step fused into preceding projection's epilogue) =====
    project(c,  yb,  EPI_FINAL_PGD);   // x1 = proj(c); y1 = x1 - a(x1-c)
    project(yb, xb,  EPI_FINAL_PGD);   // x2 = proj(y1); y2 = ...
    project(xb, yb,  EPI_FINAL_PGD);   // x3 = proj(y2); y3 = ...
    project(yb, out, EPI_ADD_D_ROW);   // x4 = proj(y3) -> out
}